// round 1
// baseline (speedup 1.0000x reference)
#include <cuda_runtime.h>

#define NN 4096
#define BB 2
#define TILE 128
#define T_TILES (NN / TILE)                      // 32
#define PAIRS_PER_B (T_TILES * (T_TILES + 1) / 2) // 528
#define GRID_BLKS (BB * PAIRS_PER_B)             // 1056
#define THREADS 256

__device__ double g_partials[GRID_BLKS];

__global__ __launch_bounds__(THREADS)
void lddt_tile_kernel(const float* __restrict__ x, const float* __restrict__ xg) {
    __shared__ float4 sAx[TILE], sAg[TILE], sBx[TILE], sBg[TILE];

    int blk = blockIdx.x;
    int b = blk / PAIRS_PER_B;
    int k = blk % PAIRS_PER_B;
    int ti = 0;
    while (k >= T_TILES - ti) { k -= T_TILES - ti; ti++; }
    int tj = ti + k;
    bool diag = (ti == tj);

    int tid = threadIdx.x;

    // Load the two 128-point tiles (x and xGT) into smem as float4.
    {
        int which = tid >> 7;          // 0 -> tile A (rows), 1 -> tile B (cols)
        int r = tid & 127;
        int tile = which ? tj : ti;
        int g = b * NN + tile * TILE + r;
        const float* px = x + 3 * g;
        const float* pg = xg + 3 * g;
        float4 vx = make_float4(px[0], px[1], px[2], 0.f);
        float4 vg = make_float4(pg[0], pg[1], pg[2], 0.f);
        if (which) { sBx[r] = vx; sBg[r] = vg; }
        else       { sAx[r] = vx; sAg[r] = vg; }
    }
    __syncthreads();

    int r = tid & 127;       // row within tile A (held in registers)
    int half = tid >> 7;     // which 64-column half of tile B
    float4 ax = sAx[r];
    float4 ag = sAg[r];

    // exp(-c) constants: sigmoid(c - d) = 1 / (1 + e^d * e^-c)
    const float K0 = 0.60653065971263342f;   // exp(-0.5)
    const float K1 = 0.36787944117144233f;   // exp(-1)
    const float K2 = 0.13533528323661270f;   // exp(-2)
    const float K3 = 0.018315638888734179f;  // exp(-4)

    float acc = 0.f;
    int m0 = half * 64;

#pragma unroll 8
    for (int mi = 0; mi < 64; mi++) {
        int m = m0 + mi;
        float4 bx = sBx[m];
        float4 bg = sBg[m];
        float dx = ax.x - bx.x, dy = ax.y - bx.y, dz = ax.z - bx.z;
        float d2  = fmaf(dx, dx, fmaf(dy, dy, dz * dz));
        float gx = ag.x - bg.x, gy = ag.y - bg.y, gz = ag.z - bg.z;
        float d2g = fmaf(gx, gx, fmaf(gy, gy, gz * gz));
        float delta = fabsf(d2g - d2);
        float e = __expf(delta);   // one MUFU.EX2 path for all four sigmoids
        float s = __fdividef(1.f, fmaf(e, K0, 1.f))
                + __fdividef(1.f, fmaf(e, K1, 1.f))
                + __fdividef(1.f, fmaf(e, K2, 1.f))
                + __fdividef(1.f, fmaf(e, K3, 1.f));
        // upper triangle only; diagonal tiles keep m > r (also excludes l==m)
        bool valid = (!diag) || (m > r);
        acc += valid ? s : 0.f;
    }

    // block reduction (deterministic per block)
    for (int o = 16; o > 0; o >>= 1)
        acc += __shfl_down_sync(0xffffffffu, acc, o);
    __shared__ float warp_sums[THREADS / 32];
    if ((tid & 31) == 0) warp_sums[tid >> 5] = acc;
    __syncthreads();
    if (tid == 0) {
        float s = 0.f;
        for (int i = 0; i < THREADS / 32; i++) s += warp_sums[i];
        g_partials[blockIdx.x] = (double)s;   // fixed slot: no atomics, deterministic
    }
}

__global__ void lddt_finalize_kernel(float* __restrict__ out) {
    __shared__ double sh[256];
    int tid = threadIdx.x;
    double s = 0.0;
    for (int i = tid; i < GRID_BLKS; i += 256) s += g_partials[i];
    sh[tid] = s;
    __syncthreads();
    for (int o = 128; o > 0; o >>= 1) {
        if (tid < o) sh[tid] += sh[tid + o];
        __syncthreads();
    }
    if (tid == 0) {
        double total = 2.0 * sh[0];                      // off-diagonal sum (sym doubled)
        double denom = (double)BB * NN * (NN - 1);       // == sum(c_lm)
        double lddt = 0.25 * total / denom;
        out[0] = (float)(1.0 - lddt);
    }
}

extern "C" void kernel_launch(void* const* d_in, const int* in_sizes, int n_in,
                              void* d_out, int out_size) {
    const float* x  = (const float*)d_in[0];   // x_l   [2,4096,3] f32
    const float* xg = (const float*)d_in[1];   // xGT_l [2,4096,3] f32
    // d_in[2], d_in[3] (is_dna, is_rna) are dead: the mask reduces to ~eye.
    float* out = (float*)d_out;

    lddt_tile_kernel<<<GRID_BLKS, THREADS>>>(x, xg);
    lddt_finalize_kernel<<<1, 256>>>(out);
}

// round 3
// speedup vs baseline: 1.5161x; 1.5161x over previous
#include <cuda_runtime.h>

#define NN 4096
#define BB 2
#define TILE 128
#define T_TILES (NN / TILE)                       // 32
#define PAIRS_PER_B (T_TILES * (T_TILES + 1) / 2) // 528
#define GRID_BLKS (BB * PAIRS_PER_B)              // 1056
#define THREADS 256

// Fixed-point accumulator (2^30 scale): integer adds are associative ->
// deterministic across graph replays. Both reset themselves every launch.
__device__ unsigned long long g_accum = 0ULL;
__device__ unsigned int g_count = 0u;

// sqrt(log2(e)): pre-scales coords so squared distances are already in
// log2 domain -> EX2 directly gives exp(delta).
#define SQRT_LOG2E 1.20112240878645217f
#define DELTA_CLAMP 28.8539008177792681f   // 20 * log2(e)

// P/Q coefficients for sum of 4 sigmoids: sum_i 1/(1+k_i*e), k_i = exp(-c_i)
#define Q1 1.12806102370722699f
#define Q2 0.37532792283466833f
#define Q3 0.03669947538826920f
#define Q4 0.00055308437014783f
#define P0 4.0f
#define P1 3.38418307112168097f
#define P2 0.75065584566933666f
#define P3 0.03669947538826920f

// Single MUFU.EX2 regardless of compile flags.
__device__ __forceinline__ float ex2_approx(float x) {
    float r;
    asm("ex2.approx.f32 %0, %1;" : "=f"(r) : "f"(x));
    return r;
}

__global__ __launch_bounds__(THREADS)
void lddt_fused_kernel(const float* __restrict__ x, const float* __restrict__ xg,
                       float* __restrict__ out) {
    __shared__ float4 sAx[TILE], sAg[TILE], sBx[TILE], sBg[TILE];

    int blk = blockIdx.x;
    int b = blk / PAIRS_PER_B;
    int k = blk % PAIRS_PER_B;
    int ti = 0;
    while (k >= T_TILES - ti) { k -= T_TILES - ti; ti++; }
    int tj = ti + k;
    bool diag = (ti == tj);

    int tid = threadIdx.x;

    // Load the two 128-point tiles into smem, pre-scaled by sqrt(log2 e).
    {
        int which = tid >> 7;          // 0 -> tile A (rows), 1 -> tile B (cols)
        int r = tid & 127;
        int tile = which ? tj : ti;
        int g = b * NN + tile * TILE + r;
        const float* px = x + 3 * g;
        const float* pg = xg + 3 * g;
        float4 vx = make_float4(px[0] * SQRT_LOG2E, px[1] * SQRT_LOG2E,
                                px[2] * SQRT_LOG2E, 0.f);
        float4 vg = make_float4(pg[0] * SQRT_LOG2E, pg[1] * SQRT_LOG2E,
                                pg[2] * SQRT_LOG2E, 0.f);
        if (which) { sBx[r] = vx; sBg[r] = vg; }
        else       { sAx[r] = vx; sAg[r] = vg; }
    }
    __syncthreads();

    int r = tid & 127;       // row within tile A
    int half = tid >> 7;     // which 64-column half of tile B
    float4 ax = sAx[r];
    float4 ag = sAg[r];

    float acc = 0.f;
    int m0 = half * 64;

#pragma unroll 16
    for (int mi = 0; mi < 64; mi++) {
        int m = m0 + mi;
        float4 bx = sBx[m];
        float4 bg = sBg[m];
        float dx = ax.x - bx.x, dy = ax.y - bx.y, dz = ax.z - bx.z;
        float d2  = fmaf(dx, dx, fmaf(dy, dy, dz * dz));
        float gx = ag.x - bg.x, gy = ag.y - bg.y, gz = ag.z - bg.z;
        float d2g = fmaf(gx, gx, fmaf(gy, gy, gz * gz));
        // delta in log2 domain, clamped (abs folds into FMNMX source modifier)
        float t = d2g - d2;
        float dl = fminf(fabsf(t), DELTA_CLAMP);
        float e = ex2_approx(dl);       // = exp(delta), one MUFU.EX2
        // sum of 4 sigmoids as a single rational P(e)/Q(e): one MUFU.RCP
        float q = fmaf(fmaf(fmaf(fmaf(Q4, e, Q3), e, Q2), e, Q1), e, 1.f);
        float p = fmaf(fmaf(fmaf(P3, e, P2), e, P1), e, P0);
        float s = __fdividef(p, q);
        bool valid = (!diag) || (m > r);   // strict upper triangle on diag tiles
        acc += valid ? s : 0.f;
    }

    // Deterministic block reduction
    for (int o = 16; o > 0; o >>= 1)
        acc += __shfl_down_sync(0xffffffffu, acc, o);
    __shared__ float warp_sums[THREADS / 32];
    if ((tid & 31) == 0) warp_sums[tid >> 5] = acc;
    __syncthreads();

    if (tid == 0) {
        float s = 0.f;
        for (int i = 0; i < THREADS / 32; i++) s += warp_sums[i];
        // fixed-point: scale 2^30 (block sum <= 65536 -> fits with margin)
        unsigned long long q30 = (unsigned long long)((double)s * 1073741824.0 + 0.5);
        atomicAdd(&g_accum, q30);
        __threadfence();
        unsigned int old = atomicInc(&g_count, GRID_BLKS - 1);  // wraps to 0
        if (old == GRID_BLKS - 1) {
            // last block: read + reset accumulator for the next graph replay
            unsigned long long total_q30 = atomicExch(&g_accum, 0ULL);
            double total = 2.0 * ((double)total_q30 * (1.0 / 1073741824.0));
            double denom = (double)BB * NN * (NN - 1);
            out[0] = (float)(1.0 - 0.25 * total / denom);
        }
    }
}

extern "C" void kernel_launch(void* const* d_in, const int* in_sizes, int n_in,
                              void* d_out, int out_size) {
    const float* x  = (const float*)d_in[0];   // x_l   [2,4096,3] f32
    const float* xg = (const float*)d_in[1];   // xGT_l [2,4096,3] f32
    // d_in[2], d_in[3] (is_dna, is_rna) are dead: the mask reduces to ~eye.
    float* out = (float*)d_out;

    lddt_fused_kernel<<<GRID_BLKS, THREADS>>>(x, xg, out);
}

// round 4
// speedup vs baseline: 1.7975x; 1.1856x over previous
#include <cuda_runtime.h>

#define NN 4096
#define BB 2
#define TILE 128
#define T_TILES (NN / TILE)                       // 32
#define PAIRS_PER_B (T_TILES * (T_TILES + 1) / 2) // 528
#define GRID_BLKS (BB * PAIRS_PER_B)              // 1056
#define THREADS 256

// Fixed-point accumulator (2^30 scale): integer adds are associative ->
// deterministic across graph replays. Self-resetting every launch.
__device__ unsigned long long g_accum = 0ULL;
__device__ unsigned int g_count = 0u;

// Coordinates pre-scaled by sqrt(2*log2(e)) so a'.b' = 2*log2e*(a.b);
// w' = log2e*(|xg|^2-|x|^2) = 0.5*(|xg'|^2-|x'|^2).
// Then t = w'_a + w'_b + a'.b' - ag'.bg' = log2e*(d2g - d2)  (log2 domain).
#define COORD_SCALE 1.69864360f
#define DELTA_CLAMP 28.8539008f            // 20 * log2(e)

// P/Q coefficients: sum of 4 sigmoids = P(e)/Q(e), e = exp(delta)
#define Q1 1.12806102370722699f
#define Q2 0.37532792283466833f
#define Q3 0.03669947538826920f
#define Q4 0.00055308437014783f
#define P0 4.0f
#define P1 3.38418307112168097f
#define P2 0.75065584566933666f
#define P3 0.03669947538826920f

// sum of 4 sigmoids at delta=0 (diagonal pairs), double precision
#define S0_DIAG 3.2163287778476503

__device__ __forceinline__ float ex2_approx(float x) {
    float r;
    asm("ex2.approx.f32 %0, %1;" : "=f"(r) : "f"(x));
    return r;
}

__global__ __launch_bounds__(THREADS)
void lddt_fused_kernel(const float* __restrict__ x, const float* __restrict__ xg,
                       float* __restrict__ out) {
    // B-side tiles: s1 = (bx,by,bz,wb), s2 = (bgx,bgy,bgz,-)
    __shared__ float4 sA1[TILE], sA2[TILE], sB1[TILE], sB2[TILE];

    int blk = blockIdx.x;
    int b = blk / PAIRS_PER_B;
    int k = blk % PAIRS_PER_B;
    int ti = 0;
    while (k >= T_TILES - ti) { k -= T_TILES - ti; ti++; }
    int tj = ti + k;
    bool diag = (ti == tj);

    int tid = threadIdx.x;

    // ── Load + precompute: 128 A points (tid<128), 128 B points (tid>=128)
    {
        int which = tid >> 7;
        int r = tid & 127;
        int tile = which ? tj : ti;
        int g = b * NN + tile * TILE + r;
        const float* px = x + 3 * g;
        const float* pg = xg + 3 * g;
        float sx = px[0] * COORD_SCALE, sy = px[1] * COORD_SCALE, sz = px[2] * COORD_SCALE;
        float gx = pg[0] * COORD_SCALE, gy = pg[1] * COORD_SCALE, gz = pg[2] * COORD_SCALE;
        float w = 0.5f * (fmaf(gx, gx, fmaf(gy, gy, gz * gz))
                        - fmaf(sx, sx, fmaf(sy, sy, sz * sz)));
        float4 v1 = make_float4(sx, sy, sz, w);
        float4 v2 = make_float4(gx, gy, gz, 0.f);
        if (which) { sB1[r] = v1; sB2[r] = v2; }
        else       { sA1[r] = v1; sA2[r] = v2; }
    }
    __syncthreads();

    // ── Register blocking: 4 rows per thread (stride 32), 16-column strip.
    int r0 = tid & 31;          // rows r0, r0+32, r0+64, r0+96
    int cs = (tid >> 5) * 16;   // column strip start (warp-uniform -> LDS broadcast)

    float ax[4], ay[4], az[4], aw[4];   // A coords + w
    float nx[4], ny[4], nz[4];          // negated A gt coords
#pragma unroll
    for (int i = 0; i < 4; i++) {
        int r = r0 + 32 * i;
        float4 v1 = sA1[r];
        float4 v2 = sA2[r];
        ax[i] = v1.x; ay[i] = v1.y; az[i] = v1.z; aw[i] = v1.w;
        nx[i] = -v2.x; ny[i] = -v2.y; nz[i] = -v2.z;
    }

    float acc = 0.f;
#pragma unroll
    for (int c = 0; c < 16; c++) {
        float4 b1 = sB1[cs + c];        // (bx,by,bz,wb) broadcast within warp
        float4 b2 = sB2[cs + c];        // (bgx,bgy,bgz,-)
#pragma unroll
        for (int i = 0; i < 4; i++) {
            float t = fmaf(ax[i], b1.x,
                      fmaf(ay[i], b1.y,
                      fmaf(az[i], b1.z,
                      fmaf(nx[i], b2.x,
                      fmaf(ny[i], b2.y,
                      fmaf(nz[i], b2.z, aw[i] + b1.w))))));
            float dl = fminf(fabsf(t), DELTA_CLAMP);
            float e = ex2_approx(dl);                       // exp(delta)
            float q = fmaf(fmaf(fmaf(fmaf(Q4, e, Q3), e, Q2), e, Q1), e, 1.f);
            float p = fmaf(fmaf(fmaf(P3, e, P2), e, P1), e, P0);
            acc += __fdividef(p, q);                        // RCP + FMUL
        }
    }

    // ── Deterministic block reduction
    for (int o = 16; o > 0; o >>= 1)
        acc += __shfl_down_sync(0xffffffffu, acc, o);
    __shared__ float warp_sums[THREADS / 32];
    if ((tid & 31) == 0) warp_sums[tid >> 5] = acc;
    __syncthreads();

    if (tid == 0) {
        float s = 0.f;
        for (int i = 0; i < THREADS / 32; i++) s += warp_sums[i];
        // fixed-point q30; off-diagonal tiles appear twice by symmetry
        unsigned long long q30 = (unsigned long long)((double)s * 1073741824.0 + 0.5);
        if (!diag) q30 *= 2ULL;
        atomicAdd(&g_accum, q30);
        __threadfence();
        unsigned int old = atomicInc(&g_count, GRID_BLKS - 1);  // wraps to 0
        if (old == GRID_BLKS - 1) {
            unsigned long long total_q30 = atomicExch(&g_accum, 0ULL);
            double total = (double)total_q30 * (1.0 / 1073741824.0)
                         - (double)(BB * NN) * S0_DIAG;       // remove l==m pairs
            double denom = (double)BB * NN * (NN - 1);
            out[0] = (float)(1.0 - 0.25 * total / denom);
        }
    }
}

extern "C" void kernel_launch(void* const* d_in, const int* in_sizes, int n_in,
                              void* d_out, int out_size) {
    const float* x  = (const float*)d_in[0];   // x_l   [2,4096,3] f32
    const float* xg = (const float*)d_in[1];   // xGT_l [2,4096,3] f32
    // d_in[2], d_in[3] (is_dna, is_rna) are dead: the mask reduces to ~eye.
    float* out = (float*)d_out;

    lddt_fused_kernel<<<GRID_BLKS, THREADS>>>(x, xg, out);
}